// round 1
// baseline (speedup 1.0000x reference)
#include <cuda_runtime.h>

// Shapes (fixed for this problem)
#define NHEAD 4
#define ATT   16
#define COLD  64     // query feature dim
#define AISD  64     // action feature dim
#define MDIM  256    // NHEAD * AISD
#define SKMAX 200
#define BMAX  8192

// Scratch (device globals — no runtime allocation)
__device__ float g_QK[COLD * MDIM];            // 64 KB
__device__ float g_W[(size_t)BMAX * MDIM];     // 8 MB
__device__ float g_ctx[(size_t)BMAX * MDIM];   // 8 MB

// ---------------------------------------------------------------------------
// K0: QK[i][h*64+a] = (1/8) * sum_j Q[i][h*16+j] * K[a][h*16+j]
// grid 64 (one block per i), 256 threads (one per (h,a))
// ---------------------------------------------------------------------------
__global__ void k0_qk(const float* __restrict__ Q, const float* __restrict__ K) {
    int i = blockIdx.x;
    int m = threadIdx.x;          // m = h*64 + a
    int h = m >> 6, a = m & 63;
    float s = 0.f;
#pragma unroll
    for (int j = 0; j < ATT; j++)
        s += Q[i * 64 + h * ATT + j] * K[a * 64 + h * ATT + j];
    g_QK[i * MDIM + m] = 0.125f * s;
}

// ---------------------------------------------------------------------------
// K1: W[b][m] = sum_i query[b][i] * QK[i][m].  16 batches per block.
// ---------------------------------------------------------------------------
__global__ void k1_w(const float* __restrict__ query, int B) {
    __shared__ float4 qs[16][16];   // 16 batches x 64 floats
    int b0 = blockIdx.x * 16;
    int t = threadIdx.x;

    int lb = t >> 4;                // batch within block for this load
    if (b0 + lb < B) {
        const float4* src = (const float4*)(query + (size_t)(b0 + lb) * 64);
        qs[lb][t & 15] = src[t & 15];
    }
    __syncthreads();

    float acc[16];
#pragma unroll
    for (int b = 0; b < 16; b++) acc[b] = 0.f;

#pragma unroll
    for (int i4 = 0; i4 < 16; i4++) {
        float qk0 = g_QK[(i4 * 4 + 0) * MDIM + t];
        float qk1 = g_QK[(i4 * 4 + 1) * MDIM + t];
        float qk2 = g_QK[(i4 * 4 + 2) * MDIM + t];
        float qk3 = g_QK[(i4 * 4 + 3) * MDIM + t];
#pragma unroll
        for (int b = 0; b < 16; b++) {
            float4 q4 = qs[b][i4];
            acc[b] += q4.x * qk0 + q4.y * qk1 + q4.z * qk2 + q4.w * qk3;
        }
    }
#pragma unroll
    for (int b = 0; b < 16; b++)
        if (b0 + b < B)
            g_W[(size_t)(b0 + b) * MDIM + t] = acc[b];
}

// ---------------------------------------------------------------------------
// K2: main attention kernel. One CTA (256 thr) per batch element.
// smem: swizzled action tile [200][64] + W row + scores + inv-sums.
// ---------------------------------------------------------------------------
#define SA_FLOATS (SKMAX * 64)                 // 12800
#define SW_OFF    SA_FLOATS                    // 256 floats
#define SC_OFF    (SW_OFF + MDIM)              // 4 * 208 floats
#define SINV_OFF  (SC_OFF + 4 * 208)           // 4 floats
#define SMEM_FLOATS (SINV_OFF + 16)
#define SMEM_BYTES  (SMEM_FLOATS * 4)

extern __shared__ float s_dyn[];

__global__ __launch_bounds__(256, 4) void k2_attn(const float* __restrict__ act, int nsk) {
    float* sa   = s_dyn;
    float* sw   = s_dyn + SW_OFF;
    float* sc   = s_dyn + SC_OFF;
    float* sinv = s_dyn + SINV_OFF;

    int b = blockIdx.x;
    int t = threadIdx.x;

    // W row for this batch
    sw[t] = g_W[(size_t)b * MDIM + t];

    // Load action tile, XOR-swizzled per 16B chunk: chunk' = c ^ (sk & 15)
    {
        const float4* ga = (const float4*)(act + (size_t)b * nsk * 64);
        int total = nsk * 16;
#pragma unroll 4
        for (int idx = t; idx < total; idx += 256) {
            float4 v = ga[idx];
            int sk = idx >> 4, c = idx & 15;
            *(float4*)(sa + sk * 64 + ((c ^ (sk & 15)) << 2)) = v;
        }
    }
    __syncthreads();

    // ---- scores: thread t handles sk = t (t < nsk) ----
    if (t < nsk) {
        int sk = t;
        const float4* w4 = (const float4*)sw;  // w4[h*16 + i]
        float a0 = 0.f, a1 = 0.f, a2 = 0.f, a3 = 0.f;
#pragma unroll
        for (int i = 0; i < 16; i++) {
            float4 av = *(const float4*)(sa + sk * 64 + ((i ^ (sk & 15)) << 2));
            float4 w0 = w4[0 * 16 + i];
            float4 w1 = w4[1 * 16 + i];
            float4 w2 = w4[2 * 16 + i];
            float4 w3 = w4[3 * 16 + i];
            a0 += av.x * w0.x + av.y * w0.y + av.z * w0.z + av.w * w0.w;
            a1 += av.x * w1.x + av.y * w1.y + av.z * w1.z + av.w * w1.w;
            a2 += av.x * w2.x + av.y * w2.y + av.z * w2.z + av.w * w2.w;
            a3 += av.x * w3.x + av.y * w3.y + av.z * w3.z + av.w * w3.w;
        }
        sc[0 * 208 + sk] = a0;
        sc[1 * 208 + sk] = a1;
        sc[2 * 208 + sk] = a2;
        sc[3 * 208 + sk] = a3;
    }
    __syncthreads();

    // ---- softmax: warp h handles head h ----
    {
        int wid = t >> 5, lane = t & 31;
        if (wid < NHEAD) {
            float* row = sc + wid * 208;
            float m = -1e30f;
            for (int sk = lane; sk < nsk; sk += 32) m = fmaxf(m, row[sk]);
#pragma unroll
            for (int o = 16; o; o >>= 1) m = fmaxf(m, __shfl_xor_sync(0xffffffffu, m, o));
            float s = 0.f;
            for (int sk = lane; sk < nsk; sk += 32) {
                float p = __expf(row[sk] - m);
                row[sk] = p;
                s += p;
            }
#pragma unroll
            for (int o = 16; o; o >>= 1) s += __shfl_xor_sync(0xffffffffu, s, o);
            if (lane == 0) sinv[wid] = 1.f / s;
        }
    }
    __syncthreads();

    // ---- ctx: ctx[h][d] = sum_sk p[h][sk] * action[sk][d] ----
    // thread: sg = t & 15 (sk chunk of 13), c4 = t >> 4 (d chunk of 4)
    int sg = t & 15, c4 = t >> 4;
    float4 c0 = {0, 0, 0, 0}, c1 = {0, 0, 0, 0}, c2 = {0, 0, 0, 0}, c3 = {0, 0, 0, 0};
    {
        int sk0 = sg * 13;
        int sk1 = sk0 + 13; if (sk1 > nsk) sk1 = nsk;
        for (int sk = sk0; sk < sk1; sk++) {
            float4 av = *(const float4*)(sa + sk * 64 + ((c4 ^ (sk & 15)) << 2));
            float p0 = sc[0 * 208 + sk];
            float p1 = sc[1 * 208 + sk];
            float p2 = sc[2 * 208 + sk];
            float p3 = sc[3 * 208 + sk];
            c0.x += p0 * av.x; c0.y += p0 * av.y; c0.z += p0 * av.z; c0.w += p0 * av.w;
            c1.x += p1 * av.x; c1.y += p1 * av.y; c1.z += p1 * av.z; c1.w += p1 * av.w;
            c2.x += p2 * av.x; c2.y += p2 * av.y; c2.z += p2 * av.z; c2.w += p2 * av.w;
            c3.x += p3 * av.x; c3.y += p3 * av.y; c3.z += p3 * av.z; c3.w += p3 * av.w;
        }
    }
    __syncthreads();   // action tile dead; reuse sa for partials

    // partial layout (swizzled, conflict-free write + read):
    // float4 slot: sg*64 + h*16 + (c4 ^ sg)
    {
        float4* part = (float4*)sa;
        part[sg * 64 + 0 * 16 + (c4 ^ sg)] = c0;
        part[sg * 64 + 1 * 16 + (c4 ^ sg)] = c1;
        part[sg * 64 + 2 * 16 + (c4 ^ sg)] = c2;
        part[sg * 64 + 3 * 16 + (c4 ^ sg)] = c3;
    }
    __syncthreads();

    // reduce over 16 sk-groups: thread t -> (h = t>>6, d = t&63)
    {
        int h = t >> 6, d = t & 63;
        int rc4 = d >> 2, e = d & 3;
        float r = 0.f;
#pragma unroll
        for (int g = 0; g < 16; g++)
            r += sa[(g * 64 + h * 16 + (rc4 ^ g)) * 4 + e];
        g_ctx[(size_t)b * MDIM + t] = r * sinv[h];
    }
}

// ---------------------------------------------------------------------------
// K3: out[b][c] = sum_a ctx[b][h(c)*64+a] * V[a][c].  4 batches per block.
// ---------------------------------------------------------------------------
__global__ void k3_out(const float* __restrict__ V, float* __restrict__ out, int B) {
    __shared__ float cs[4][MDIM];
    int b0 = blockIdx.x * 4;
    int t = threadIdx.x;
#pragma unroll
    for (int b = 0; b < 4; b++)
        if (b0 + b < B)
            cs[b][t] = g_ctx[(size_t)(b0 + b) * MDIM + t];
    __syncthreads();

    int bb = t >> 6, c = t & 63, h = c >> 4;
    float acc = 0.f;
    const float4* cp4 = (const float4*)&cs[bb][h * 64];
#pragma unroll
    for (int a4 = 0; a4 < 16; a4++) {
        float4 cv = cp4[a4];
        acc += cv.x * V[(a4 * 4 + 0) * 64 + c];
        acc += cv.y * V[(a4 * 4 + 1) * 64 + c];
        acc += cv.z * V[(a4 * 4 + 2) * 64 + c];
        acc += cv.w * V[(a4 * 4 + 3) * 64 + c];
    }
    if (b0 + bb < B)
        out[(size_t)(b0 + bb) * 64 + c] = acc;
}

// ---------------------------------------------------------------------------
extern "C" void kernel_launch(void* const* d_in, const int* in_sizes, int n_in,
                              void* d_out, int out_size) {
    const float* query = (const float*)d_in[0];   // [B,1,64]
    const float* act   = (const float*)d_in[1];   // [B,SK,64]
    const float* Q     = (const float*)d_in[2];   // [64,64]
    const float* K     = (const float*)d_in[3];   // [64,64]
    const float* V     = (const float*)d_in[4];   // [64,64]
    float* out = (float*)d_out;

    int B   = in_sizes[0] / COLD;
    int nsk = in_sizes[1] / (B * AISD);

    cudaFuncSetAttribute(k2_attn, cudaFuncAttributeMaxDynamicSharedMemorySize, SMEM_BYTES);

    k0_qk<<<COLD, 256>>>(Q, K);
    k1_w<<<(B + 15) / 16, 256>>>(query, B);
    k2_attn<<<B, 256, SMEM_BYTES>>>(act, nsk);
    k3_out<<<(B + 3) / 4, 256>>>(V, out, B);
}

// round 2
// speedup vs baseline: 1.0389x; 1.0389x over previous
#include <cuda_runtime.h>
#include <cuda_fp16.h>

// Shapes (fixed for this problem)
#define NHEAD 4
#define ATT   16
#define COLD  64
#define AISD  64
#define MDIM  256    // NHEAD * AISD
#define SKPAD 208
#define BMAX  8192

// Scratch (device globals — no runtime allocation)
__device__ float g_QK[COLD * MDIM];            // 64 KB
__device__ float g_W[(size_t)BMAX * MDIM];     // 8 MB

// ---------------------------------------------------------------------------
// K0: QK[i][h*64+a] = (1/8) * sum_j Q[i][h*16+j] * K[a][h*16+j]
// ---------------------------------------------------------------------------
__global__ void k0_qk(const float* __restrict__ Q, const float* __restrict__ K) {
    int i = blockIdx.x;
    int m = threadIdx.x;          // m = h*64 + a
    int h = m >> 6, a = m & 63;
    float s = 0.f;
#pragma unroll
    for (int j = 0; j < ATT; j++)
        s += Q[i * 64 + h * ATT + j] * K[a * 64 + h * ATT + j];
    g_QK[i * MDIM + m] = 0.125f * s;
}

// ---------------------------------------------------------------------------
// K1: W[b][m] = sum_i query[b][i] * QK[i][m].  16 batches per block.
// ---------------------------------------------------------------------------
__global__ void k1_w(const float* __restrict__ query, int B) {
    __shared__ float4 qs[16][16];
    int b0 = blockIdx.x * 16;
    int t = threadIdx.x;

    int lb = t >> 4;
    if (b0 + lb < B) {
        const float4* src = (const float4*)(query + (size_t)(b0 + lb) * 64);
        qs[lb][t & 15] = src[t & 15];
    }
    __syncthreads();

    float acc[16];
#pragma unroll
    for (int b = 0; b < 16; b++) acc[b] = 0.f;

#pragma unroll
    for (int i4 = 0; i4 < 16; i4++) {
        float qk0 = g_QK[(i4 * 4 + 0) * MDIM + t];
        float qk1 = g_QK[(i4 * 4 + 1) * MDIM + t];
        float qk2 = g_QK[(i4 * 4 + 2) * MDIM + t];
        float qk3 = g_QK[(i4 * 4 + 3) * MDIM + t];
#pragma unroll
        for (int b = 0; b < 16; b++) {
            float4 q4 = qs[b][i4];
            acc[b] += q4.x * qk0 + q4.y * qk1 + q4.z * qk2 + q4.w * qk3;
        }
    }
#pragma unroll
    for (int b = 0; b < 16; b++)
        if (b0 + b < B)
            g_W[(size_t)(b0 + b) * MDIM + t] = acc[b];
}

// ---------------------------------------------------------------------------
// K2 fused: per-batch attention + output projection.
// smem: fp16 swizzled action tile + W row + scores/ctx + partials.
// ---------------------------------------------------------------------------
#define SA_BYTES   (SKPAD * 64 * 2)                 // 26624
#define SW_OFF     SA_BYTES
#define SC_OFF     (SW_OFF + 1024)                  // 4*208 floats = 3328B
#define SINV_OFF   (SC_OFF + 3328)
#define PART_OFF   (SINV_OFF + 32)                  // 8*144 floats = 4608B
#define SMEM_BYTES (PART_OFF + 4608)

extern __shared__ char s_raw[];

__global__ __launch_bounds__(256, 5) void k2_fused(const float* __restrict__ act,
                                                   const float* __restrict__ V,
                                                   float* __restrict__ out, int nsk) {
    __half* sa   = (__half*)s_raw;
    float*  sw   = (float*)(s_raw + SW_OFF);
    float*  sc   = (float*)(s_raw + SC_OFF);
    float*  sinv = (float*)(s_raw + SINV_OFF);
    float*  part = (float*)(s_raw + PART_OFF);

    int b = blockIdx.x;
    int t = threadIdx.x;

    // W row for this batch (fp32)
    sw[t] = g_W[(size_t)b * MDIM + t];

    // ---- Phase A: load action tile, convert to fp16, XOR-swizzled 16B chunks
    {
        const float4* ga = (const float4*)(act + (size_t)b * nsk * 64);
        int ngroups = nsk * 8;        // groups of 8 floats
#pragma unroll 2
        for (int g = t; g < ngroups; g += 256) {
            float4 fa = ga[2 * g];
            float4 fb = ga[2 * g + 1];
            __half2 h0 = __floats2half2_rn(fa.x, fa.y);
            __half2 h1 = __floats2half2_rn(fa.z, fa.w);
            __half2 h2 = __floats2half2_rn(fb.x, fb.y);
            __half2 h3 = __floats2half2_rn(fb.z, fb.w);
            uint4 pk;
            pk.x = *(const unsigned*)&h0;
            pk.y = *(const unsigned*)&h1;
            pk.z = *(const unsigned*)&h2;
            pk.w = *(const unsigned*)&h3;
            int sk = g >> 3, c = g & 7;
            *(uint4*)(sa + sk * 64 + ((c ^ (sk & 7)) << 3)) = pk;
        }
    }
    __syncthreads();

    // ---- Phase B: scores. Threads 0..127 each handle sk=t and sk=t+128.
    if (t < 128) {
        int sk1 = t;
        int sk2 = t + 128;
        bool v1 = sk1 < nsk;
        bool v2 = sk2 < nsk;
        const float4* w4 = (const float4*)sw;   // w4[h*16 + q]
        float a1[4] = {0, 0, 0, 0};
        float a2[4] = {0, 0, 0, 0};
#pragma unroll
        for (int i = 0; i < 8; i++) {
            float d1[8], d2[8];
            if (v1) {
                uint4 av = *(const uint4*)(sa + sk1 * 64 + ((i ^ (sk1 & 7)) << 3));
                __half2* hv = (__half2*)&av;
                float2 f0 = __half22float2(hv[0]), f1 = __half22float2(hv[1]);
                float2 f2 = __half22float2(hv[2]), f3 = __half22float2(hv[3]);
                d1[0] = f0.x; d1[1] = f0.y; d1[2] = f1.x; d1[3] = f1.y;
                d1[4] = f2.x; d1[5] = f2.y; d1[6] = f3.x; d1[7] = f3.y;
            }
            if (v2) {
                uint4 av = *(const uint4*)(sa + sk2 * 64 + ((i ^ (sk2 & 7)) << 3));
                __half2* hv = (__half2*)&av;
                float2 f0 = __half22float2(hv[0]), f1 = __half22float2(hv[1]);
                float2 f2 = __half22float2(hv[2]), f3 = __half22float2(hv[3]);
                d2[0] = f0.x; d2[1] = f0.y; d2[2] = f1.x; d2[3] = f1.y;
                d2[4] = f2.x; d2[5] = f2.y; d2[6] = f3.x; d2[7] = f3.y;
            }
#pragma unroll
            for (int h = 0; h < 4; h++) {
                float4 wA = w4[h * 16 + 2 * i];
                float4 wB = w4[h * 16 + 2 * i + 1];
                if (v1)
                    a1[h] += d1[0] * wA.x + d1[1] * wA.y + d1[2] * wA.z + d1[3] * wA.w
                           + d1[4] * wB.x + d1[5] * wB.y + d1[6] * wB.z + d1[7] * wB.w;
                if (v2)
                    a2[h] += d2[0] * wA.x + d2[1] * wA.y + d2[2] * wA.z + d2[3] * wA.w
                           + d2[4] * wB.x + d2[5] * wB.y + d2[6] * wB.z + d2[7] * wB.w;
            }
        }
        if (v1) {
#pragma unroll
            for (int h = 0; h < 4; h++) sc[h * SKPAD + sk1] = a1[h];
        }
        if (v2) {
#pragma unroll
            for (int h = 0; h < 4; h++) sc[h * SKPAD + sk2] = a2[h];
        }
    }
    __syncthreads();

    // ---- Phase C: softmax, warp h per head. Leaves UNNORMALIZED p in sc,
    //      1/sum in sinv[h].
    {
        int wid = t >> 5, lane = t & 31;
        if (wid < NHEAD) {
            float* row = sc + wid * SKPAD;
            float m = -1e30f;
            for (int sk = lane; sk < nsk; sk += 32) m = fmaxf(m, row[sk]);
#pragma unroll
            for (int o = 16; o; o >>= 1) m = fmaxf(m, __shfl_xor_sync(0xffffffffu, m, o));
            float s = 0.f;
            for (int sk = lane; sk < nsk; sk += 32) {
                float p = __expf(row[sk] - m);
                row[sk] = p;
                s += p;
            }
#pragma unroll
            for (int o = 16; o; o >>= 1) s += __shfl_xor_sync(0xffffffffu, s, o);
            if (lane == 0) sinv[wid] = 1.f / s;
        }
    }
    __syncthreads();

    // ---- Phase D: ctx. Thread = (hp = t>>7 head-pair, sg = (t&127)>>3, c8 = t&7).
    //      Accumulates ctx[2 heads][8 dims] over its 13 sk values.
    {
        int hp = t >> 7;
        int local = t & 127;
        int sg = local >> 3;
        int c8 = local & 7;
        int h0 = hp * 2, h1 = hp * 2 + 1;
        float acc[16];
#pragma unroll
        for (int v = 0; v < 16; v++) acc[v] = 0.f;

        int sk0 = sg * 13;
        int sk1e = sk0 + 13; if (sk1e > nsk) sk1e = nsk;
        for (int sk = sk0; sk < sk1e; sk++) {
            uint4 av = *(const uint4*)(sa + sk * 64 + ((c8 ^ (sk & 7)) << 3));
            float p0 = sc[h0 * SKPAD + sk];
            float p1 = sc[h1 * SKPAD + sk];
            __half2* hv = (__half2*)&av;
            float2 f0 = __half22float2(hv[0]), f1 = __half22float2(hv[1]);
            float2 f2 = __half22float2(hv[2]), f3 = __half22float2(hv[3]);
            acc[0]  += p0 * f0.x; acc[1]  += p0 * f0.y;
            acc[2]  += p0 * f1.x; acc[3]  += p0 * f1.y;
            acc[4]  += p0 * f2.x; acc[5]  += p0 * f2.y;
            acc[6]  += p0 * f3.x; acc[7]  += p0 * f3.y;
            acc[8]  += p1 * f0.x; acc[9]  += p1 * f0.y;
            acc[10] += p1 * f1.x; acc[11] += p1 * f1.y;
            acc[12] += p1 * f2.x; acc[13] += p1 * f2.y;
            acc[14] += p1 * f3.x; acc[15] += p1 * f3.y;
        }
        // warp-level reduce over the 4 sk-groups in this warp (lane bits 3,4)
#pragma unroll
        for (int v = 0; v < 16; v++) {
            acc[v] += __shfl_xor_sync(0xffffffffu, acc[v], 8);
            acc[v] += __shfl_xor_sync(0xffffffffu, acc[v], 16);
        }
        int lane = t & 31, w = t >> 5;
        if (lane < 8) {
            float* pp = part + w * 144 + lane * 18;   // lane = c8
#pragma unroll
            for (int v = 0; v < 16; v++) pp[v] = acc[v];
        }
    }
    __syncthreads();

    // ---- Phase E: combine partials -> normalized ctx in sc[0..255]
    {
        int h = t >> 6, d = t & 63;
        int hp2 = h >> 1, vh = h & 1, cc8 = d >> 3, vd = d & 7;
        float s = 0.f;
#pragma unroll
        for (int j = 0; j < 4; j++)
            s += part[(4 * hp2 + j) * 144 + cc8 * 18 + vh * 8 + vd];
        sc[t] = s * sinv[h];      // sc reused as ctx[h*64 + d]
    }
    __syncthreads();

    // ---- Phase F: output projection out[c] = sum_a ctx[h(c)*64+a] * V[a][c]
    {
        int ar = t >> 6, c = t & 63;
        int h = c >> 4;
        float accv = 0.f;
        const float* vp = V + (size_t)(ar * 16) * 64 + c;
#pragma unroll
        for (int j = 0; j < 16; j++)
            accv += sc[h * 64 + ar * 16 + j] * __ldg(vp + (size_t)j * 64);
        part[ar * 68 + c] = accv;     // reuse part region (read finished above)
    }
    __syncthreads();

    if (t < 64) {
        float r = part[t] + part[68 + t] + part[136 + t] + part[204 + t];
        out[(size_t)b * 64 + t] = r;
    }
}

// ---------------------------------------------------------------------------
extern "C" void kernel_launch(void* const* d_in, const int* in_sizes, int n_in,
                              void* d_out, int out_size) {
    const float* query = (const float*)d_in[0];   // [B,1,64]
    const float* act   = (const float*)d_in[1];   // [B,SK,64]
    const float* Q     = (const float*)d_in[2];   // [64,64]
    const float* K     = (const float*)d_in[3];   // [64,64]
    const float* V     = (const float*)d_in[4];   // [64,64]
    float* out = (float*)d_out;

    int B   = in_sizes[0] / COLD;
    int nsk = in_sizes[1] / (B * AISD);
    if (nsk > SKPAD) nsk = SKPAD;   // tile capacity (problem uses 200)

    cudaFuncSetAttribute(k2_fused, cudaFuncAttributeMaxDynamicSharedMemorySize, SMEM_BYTES);

    k0_qk<<<COLD, 256>>>(Q, K);
    k1_w<<<(B + 15) / 16, 256>>>(query, B);
    k2_fused<<<B, 256, SMEM_BYTES>>>(act, V, out, nsk);
}

// round 3
// speedup vs baseline: 1.2482x; 1.2014x over previous
#include <cuda_runtime.h>
#include <cuda_fp16.h>

#define NHEAD 4
#define ATT   16
#define COLD  64
#define AISD  64
#define MDIM  256
#define SKPAD 208
#define BMAX  8192

__device__ float g_W[(size_t)BMAX * MDIM];   // 8 MB scratch

typedef unsigned long long ull;

// ---- packed fp32x2 helpers (sm_100+ PTX; ptxas never auto-fuses these) ----
__device__ __forceinline__ ull fma2(ull a, ull b, ull c) {
    ull d;
    asm("fma.rn.f32x2 %0, %1, %2, %3;" : "=l"(d) : "l"(a), "l"(b), "l"(c));
    return d;
}
__device__ __forceinline__ ull pack2(float x, float y) {
    ull r;
    asm("mov.b64 %0, {%1, %2};" : "=l"(r) : "f"(x), "f"(y));
    return r;
}
__device__ __forceinline__ float2 unpack2(ull a) {
    float2 f;
    asm("mov.b64 {%0, %1}, %2;" : "=f"(f.x), "=f"(f.y) : "l"(a));
    return f;
}
__device__ __forceinline__ ull h2f2(unsigned h) {   // half2 -> packed f32x2
    ull r;
    asm("{\n\t.reg .b16 lo, hi;\n\t.reg .f32 flo, fhi;\n\t"
        "mov.b32 {lo, hi}, %1;\n\t"
        "cvt.f32.f16 flo, lo;\n\tcvt.f32.f16 fhi, hi;\n\t"
        "mov.b64 %0, {flo, fhi};\n\t}" : "=l"(r) : "r"(h));
    return r;
}

// ---------------------------------------------------------------------------
// K1': W[b][h*64+a] = (1/8) sum_j (q[b]@Q)[h*16+j] * K[a][h*16+j]
// 16 batches per block. Replaces both k0 and old k1 (no g_QK needed).
// ---------------------------------------------------------------------------
__global__ __launch_bounds__(256) void k1_w(const float* __restrict__ query,
                                            const float* __restrict__ Q,
                                            const float* __restrict__ K, int B) {
    __shared__ float qs[16][64];
    __shared__ float qp[16][64];
    int b0 = blockIdx.x * 16, t = threadIdx.x;

    int lb = t >> 4;
    if (b0 + lb < B) {
        const float4* src = (const float4*)(query + (size_t)(b0 + lb) * 64);
        ((float4*)qs[lb])[t & 15] = src[t & 15];
    } else {
        ((float4*)qs[lb])[t & 15] = make_float4(0, 0, 0, 0);
    }
    __syncthreads();

    // qp[b][c] = sum_i qs[b][i] * Q[i][c]
    int c = t & 63, bq = t >> 6;
    float acc[4] = {0, 0, 0, 0};
    for (int i = 0; i < 64; i++) {
        float qv = Q[i * 64 + c];
#pragma unroll
        for (int k = 0; k < 4; k++) acc[k] += qs[bq * 4 + k][i] * qv;
    }
#pragma unroll
    for (int k = 0; k < 4; k++) qp[bq * 4 + k][c] = acc[k];
    __syncthreads();

    // W[b][t], t = h*64 + a
    int h = t >> 6, a = t & 63;
    const float4* K4 = (const float4*)(K + a * 64 + h * 16);
    float4 k0 = K4[0], k1 = K4[1], k2 = K4[2], k3 = K4[3];
#pragma unroll
    for (int b = 0; b < 16; b++) {
        const float4* q4 = (const float4*)(qp[b] + h * 16);
        float4 qa = q4[0], qb = q4[1], qc = q4[2], qd = q4[3];
        float wv = qa.x * k0.x + qa.y * k0.y + qa.z * k0.z + qa.w * k0.w
                 + qb.x * k1.x + qb.y * k1.y + qb.z * k1.z + qb.w * k1.w
                 + qc.x * k2.x + qc.y * k2.y + qc.z * k2.z + qc.w * k2.w
                 + qd.x * k3.x + qd.y * k3.y + qd.z * k3.z + qd.w * k3.w;
        if (b0 + b < B) g_W[(size_t)(b0 + b) * MDIM + t] = 0.125f * wv;
    }
}

// ---------------------------------------------------------------------------
// K2: fused attention + output projection, one CTA per batch element.
// ---------------------------------------------------------------------------
#define SA_BYTES   (SKPAD * 64 * 2)          // 26624: fp16 swizzled action tile
#define SW_OFF     SA_BYTES                  // 1024: W row (fp32)
#define SC_OFF     (SW_OFF + 1024)           // 3328: scores as float2[2][SKPAD]
#define SINV_OFF   (SC_OFF + 3328)           // 32
#define PART_OFF   (SINV_OFF + 32)           // 5120: 8 warps * 160 floats
#define SMEM_BYTES (PART_OFF + 5120)

extern __shared__ char s_raw[];

__global__ __launch_bounds__(256, 5) void k2_fused(const float* __restrict__ act,
                                                   const float* __restrict__ V,
                                                   float* __restrict__ out, int nsk) {
    __half* sa   = (__half*)s_raw;
    float*  sw   = (float*)(s_raw + SW_OFF);
    ull*    scu  = (ull*)(s_raw + SC_OFF);       // packed (h0,h1) / (h2,h3) scores
    float*  scf  = (float*)(s_raw + SC_OFF);
    float*  sinv = (float*)(s_raw + SINV_OFF);
    float*  part = (float*)(s_raw + PART_OFF);

    int b = blockIdx.x;
    int t = threadIdx.x;

    sw[t] = g_W[(size_t)b * MDIM + t];

    // ---- Phase A: load action tile -> fp16, XOR-swizzled 16B chunks
    {
        const float4* ga = (const float4*)(act + (size_t)b * nsk * 64);
        int ngroups = nsk * 8;
#pragma unroll 2
        for (int g = t; g < ngroups; g += 256) {
            float4 fa = ga[2 * g];
            float4 fb = ga[2 * g + 1];
            __half2 h0 = __floats2half2_rn(fa.x, fa.y);
            __half2 h1 = __floats2half2_rn(fa.z, fa.w);
            __half2 h2 = __floats2half2_rn(fb.x, fb.y);
            __half2 h3 = __floats2half2_rn(fb.z, fb.w);
            uint4 pk;
            pk.x = *(const unsigned*)&h0;
            pk.y = *(const unsigned*)&h1;
            pk.z = *(const unsigned*)&h2;
            pk.w = *(const unsigned*)&h3;
            int sk = g >> 3, cc = g & 7;
            *(uint4*)(sa + sk * 64 + ((cc ^ (sk & 7)) << 3)) = pk;
        }
    }
    __syncthreads();

    // ---- Phase B: scores with f32x2. thread t<half handles sk=t and sk=t+half.
    {
        int half = (nsk + 1) >> 1;
        if (t < half) {
            int sk1 = t, sk2 = t + half;
            bool v2 = sk2 < nsk;
            const ull* w2 = (const ull*)sw;      // pair p of head h at [h*32+p]
            ull a1[4] = {0, 0, 0, 0}, a2[4] = {0, 0, 0, 0};
#pragma unroll
            for (int i = 0; i < 8; i++) {
                uint4 av1 = *(const uint4*)(sa + sk1 * 64 + ((i ^ (sk1 & 7)) << 3));
                uint4 av2 = make_uint4(0, 0, 0, 0);
                if (v2) av2 = *(const uint4*)(sa + sk2 * 64 + ((i ^ (sk2 & 7)) << 3));
                ull d1[4] = {h2f2(av1.x), h2f2(av1.y), h2f2(av1.z), h2f2(av1.w)};
                ull d2[4] = {h2f2(av2.x), h2f2(av2.y), h2f2(av2.z), h2f2(av2.w)};
#pragma unroll
                for (int p = 0; p < 4; p++) {
#pragma unroll
                    for (int h = 0; h < 4; h++) {
                        ull w = w2[h * 32 + i * 4 + p];
                        a1[h] = fma2(d1[p], w, a1[h]);
                        a2[h] = fma2(d2[p], w, a2[h]);
                    }
                }
            }
            float s1[4], s2[4];
#pragma unroll
            for (int h = 0; h < 4; h++) {
                float2 f1 = unpack2(a1[h]); s1[h] = f1.x + f1.y;
                float2 f2 = unpack2(a2[h]); s2[h] = f2.x + f2.y;
            }
            scu[0 * SKPAD + sk1] = pack2(s1[0], s1[1]);
            scu[1 * SKPAD + sk1] = pack2(s1[2], s1[3]);
            if (v2) {
                scu[0 * SKPAD + sk2] = pack2(s2[0], s2[1]);
                scu[1 * SKPAD + sk2] = pack2(s2[2], s2[3]);
            }
        }
    }
    __syncthreads();

    // ---- Phase C: softmax, warp h per head (unnormalized p left in place)
    {
        int wid = t >> 5, lane = t & 31;
        if (wid < NHEAD) {
            int base = (wid >> 1) * SKPAD * 2 + (wid & 1);   // scf stride 2
            float m = -1e30f;
            for (int sk = lane; sk < nsk; sk += 32)
                m = fmaxf(m, scf[base + 2 * sk]);
#pragma unroll
            for (int o = 16; o; o >>= 1) m = fmaxf(m, __shfl_xor_sync(0xffffffffu, m, o));
            float s = 0.f;
            for (int sk = lane; sk < nsk; sk += 32) {
                float p = __expf(scf[base + 2 * sk] - m);
                scf[base + 2 * sk] = p;
                s += p;
            }
#pragma unroll
            for (int o = 16; o; o >>= 1) s += __shfl_xor_sync(0xffffffffu, s, o);
            if (lane == 0) sinv[wid] = 1.f / s;
        }
    }
    __syncthreads();

    // ---- Phase D: ctx partials with f32x2. thread = (hp, sg, c8).
    {
        int hp = t >> 7;
        int local = t & 127;
        int sg = local >> 3, c8 = local & 7;
        ull acc[8] = {0, 0, 0, 0, 0, 0, 0, 0};
        const ull* pu = scu + hp * SKPAD;
        int sk0 = sg * 13;
        int sk1e = sk0 + 13; if (sk1e > nsk) sk1e = nsk;
        for (int sk = sk0; sk < sk1e; sk++) {
            uint4 av = *(const uint4*)(sa + sk * 64 + ((c8 ^ (sk & 7)) << 3));
            float2 p = unpack2(pu[sk]);
            ull p0 = pack2(p.x, p.x), p1 = pack2(p.y, p.y);
            ull d0 = h2f2(av.x), d1 = h2f2(av.y), d2 = h2f2(av.z), d3 = h2f2(av.w);
            acc[0] = fma2(p0, d0, acc[0]); acc[1] = fma2(p0, d1, acc[1]);
            acc[2] = fma2(p0, d2, acc[2]); acc[3] = fma2(p0, d3, acc[3]);
            acc[4] = fma2(p1, d0, acc[4]); acc[5] = fma2(p1, d1, acc[5]);
            acc[6] = fma2(p1, d2, acc[6]); acc[7] = fma2(p1, d3, acc[7]);
        }
        float red[16];
#pragma unroll
        for (int v = 0; v < 8; v++) {
            float2 f = unpack2(acc[v]);
            red[(v >> 2) * 8 + 2 * (v & 3)]     = f.x;
            red[(v >> 2) * 8 + 2 * (v & 3) + 1] = f.y;
        }
#pragma unroll
        for (int j = 0; j < 16; j++) {
            red[j] += __shfl_xor_sync(0xffffffffu, red[j], 8);
            red[j] += __shfl_xor_sync(0xffffffffu, red[j], 16);
        }
        int lane = t & 31, w = t >> 5;
        if (lane < 8) {
            float* pp = part + w * 160 + lane * 20;
#pragma unroll
            for (int j = 0; j < 16; j++) pp[j] = red[j];
        }
    }
    __syncthreads();

    // ---- Phase E: combine partials -> normalized ctx (reuse score region)
    {
        int h = t >> 6, d = t & 63;
        int hp2 = h >> 1, vh = h & 1, cc8 = d >> 3, vd = d & 7;
        float s = 0.f;
#pragma unroll
        for (int j = 0; j < 4; j++)
            s += part[(4 * hp2 + j) * 160 + cc8 * 20 + vh * 8 + vd];
        scf[t] = s * sinv[h];     // ctx[h*64 + d]
    }
    __syncthreads();

    // ---- Phase F: out[c] = sum_a ctx[h(c)*64+a] * V[a][c]
    {
        int ar = t >> 6, c = t & 63;
        int h = c >> 4;
        float accv = 0.f;
        const float* vp = V + (size_t)(ar * 16) * 64 + c;
#pragma unroll
        for (int j = 0; j < 16; j++)
            accv += scf[h * 64 + ar * 16 + j] * __ldg(vp + (size_t)j * 64);
        part[ar * 68 + c] = accv;
    }
    __syncthreads();

    if (t < 64) {
        float r = part[t] + part[68 + t] + part[136 + t] + part[204 + t];
        out[(size_t)b * 64 + t] = r;
    }
}

// ---------------------------------------------------------------------------
extern "C" void kernel_launch(void* const* d_in, const int* in_sizes, int n_in,
                              void* d_out, int out_size) {
    const float* query = (const float*)d_in[0];   // [B,1,64]
    const float* act   = (const float*)d_in[1];   // [B,SK,64]
    const float* Q     = (const float*)d_in[2];   // [64,64]
    const float* K     = (const float*)d_in[3];   // [64,64]
    const float* V     = (const float*)d_in[4];   // [64,64]
    float* out = (float*)d_out;

    int B   = in_sizes[0] / COLD;
    int nsk = in_sizes[1] / (B * AISD);
    if (nsk > SKPAD) nsk = SKPAD;

    cudaFuncSetAttribute(k2_fused, cudaFuncAttributeMaxDynamicSharedMemorySize, SMEM_BYTES);

    k1_w<<<(B + 15) / 16, 256>>>(query, Q, K, B);
    k2_fused<<<B, 256, SMEM_BYTES>>>(act, V, out, nsk);
}